// round 1
// baseline (speedup 1.0000x reference)
#include <cuda_runtime.h>
#include <cuda_bf16.h>
#include <cstdio>

// Problem constants
#define BB   4
#define CC   256
#define CQ   32
#define HH   128
#define WW   128
#define NH   4
#define HW   (HH*WW)          // 16384
#define P    HW

// ---------------- scratch (device globals; no allocation) ----------------
__device__ float g_q [BB*CQ*HW];   // 8 MB
__device__ float g_k [BB*CQ*HW];   // 8 MB
__device__ float g_v [BB*CC*HW];   // 64 MB
__device__ float g_qT[BB*CQ*HW];   // 8 MB
__device__ float g_kT[BB*CQ*HW];   // 8 MB
__device__ float g_vT[BB*CC*HW];   // 64 MB
__device__ float g_oh[BB*CC*HW];   // 64 MB (horizontal attention output)

// ---------------- projection GEMM:  Y[b,m,p] = sum_k W[m,k]*X[b,k,p] + bias[m] ----
template<int BM,int BN,int BK,int TM,int TN>
__global__ __launch_bounds__((BM/TM)*(BN/TN))
void proj_kernel(const float* __restrict__ Wm, const float* __restrict__ bias,
                 const float* __restrict__ X, float* __restrict__ Y,
                 int M, int K, int N)
{
    __shared__ float As[BK][BM];
    __shared__ float Bs[BK][BN];
    const int NT = (BM/TM)*(BN/TN);
    int tid = threadIdx.x;
    int tx = tid % (BN/TN);
    int ty = tid / (BN/TN);
    const float* Xb = X + (size_t)blockIdx.z * K * N;
    float*       Yb = Y + (size_t)blockIdx.z * M * N;
    int m0 = blockIdx.y * BM, n0 = blockIdx.x * BN;

    float acc[TM][TN];
#pragma unroll
    for (int i=0;i<TM;i++)
#pragma unroll
        for (int j=0;j<TN;j++) acc[i][j] = 0.f;

    for (int k0 = 0; k0 < K; k0 += BK) {
#pragma unroll
        for (int i = tid; i < BM*BK; i += NT) {
            int m = i / BK, kk = i % BK;
            As[kk][m] = Wm[(size_t)(m0+m)*K + k0 + kk];
        }
#pragma unroll
        for (int i = tid; i < BK*BN; i += NT) {
            int kk = i / BN, n = i % BN;
            Bs[kk][n] = Xb[(size_t)(k0+kk)*N + n0 + n];
        }
        __syncthreads();
#pragma unroll
        for (int kk = 0; kk < BK; kk++) {
            float rm[TM], rn[TN];
#pragma unroll
            for (int i=0;i<TM;i++) rm[i] = As[kk][ty*TM+i];
#pragma unroll
            for (int j=0;j<TN;j++) rn[j] = Bs[kk][tx*TN+j];
#pragma unroll
            for (int i=0;i<TM;i++)
#pragma unroll
                for (int j=0;j<TN;j++) acc[i][j] += rm[i]*rn[j];
        }
        __syncthreads();
    }
#pragma unroll
    for (int i=0;i<TM;i++) {
        float bv = bias[m0 + ty*TM + i];
        float* yp = &Yb[(size_t)(m0+ty*TM+i)*N + n0 + tx*TN];
#pragma unroll
        for (int j=0;j<TN;j++) yp[j] = acc[i][j] + bv;
    }
}

// ---------------- per-plane 128x128 transpose ----------------
__global__ __launch_bounds__(256)
void transpose_kernel(const float* __restrict__ src, float* __restrict__ dst)
{
    __shared__ float t[32][33];
    int p  = blockIdx.z;
    int i0 = blockIdx.y*32, j0 = blockIdx.x*32;
    const float* S = src + (size_t)p*HW;
    float*       D = dst + (size_t)p*HW;
    int tx = threadIdx.x & 31;
    int ty = threadIdx.x >> 5;           // 0..7
#pragma unroll
    for (int r=0;r<32;r+=8) t[ty+r][tx] = S[(size_t)(i0+ty+r)*WW + j0+tx];
    __syncthreads();
#pragma unroll
    for (int r=0;r<32;r+=8) D[(size_t)(j0+ty+r)*WW + i0+tx] = t[tx][ty+r];
}

// ---------------- attention over one line (row or, with transposed inputs, column) ----
// Et is stored transposed: Et[key][query], row stride 132 (odd*4 → conflict-free
// softmax column walks and float4 phase-3 loads).
// mode 0: write o to outp (o_h scratch).
// mode 1: outp[idx] = gamma*(o + scr[idx]) + x[idx]  (final fused epilogue).
__global__ __launch_bounds__(256)
void attn_kernel(const float* __restrict__ q, const float* __restrict__ k,
                 const float* __restrict__ v, const float* __restrict__ scr,
                 const float* __restrict__ x, const float* __restrict__ gamma,
                 float* __restrict__ outp, int mode)
{
    extern __shared__ float sm[];
    float* qs = sm;                 // 8*128
    float* ks = sm + 1024;          // 8*128
    float* vs = sm + 2048;          // 64*128
    float* Et = sm + 2048 + 8192;   // 128*132
    float* ss = Et + 128*132;       // 128

    int tid = threadIdx.x;          // 256 threads
    int row = blockIdx.x;           // h (mode0) / w (mode1 with transposed arrays)
    int bh  = blockIdx.y;           // 0..15
    int b   = bh >> 2, hd = bh & 3;

    const float* qb = q + ((size_t)(b*CQ + hd*8 ))*HW + (size_t)row*WW;
    const float* kb = k + ((size_t)(b*CQ + hd*8 ))*HW + (size_t)row*WW;
    const float* vb = v + ((size_t)(b*CC + hd*64))*HW + (size_t)row*WW;

    for (int i = tid; i < 8*128; i += 256) {
        int c = i >> 7, j = i & 127;
        qs[i] = qb[(size_t)c*HW + j];
        ks[i] = kb[(size_t)c*HW + j];
    }
    for (int i = tid; i < 64*128; i += 256) {
        int c = i >> 7, j = i & 127;
        vs[i] = vb[(size_t)c*HW + j];
    }
    __syncthreads();

    // ---- phase 1: Et[kv][w] = sum_c qs[c][w]*ks[c][kv] (each thread 8x8 tile) ----
    {
        int w0 = (tid >> 4) * 8;    // query tile
        int v0 = (tid & 15) * 8;    // key tile
        float acc[8][8];
#pragma unroll
        for (int j=0;j<8;j++)
#pragma unroll
            for (int i=0;i<8;i++) acc[j][i] = 0.f;
#pragma unroll
        for (int c = 0; c < 8; c++) {
            float4 qa = *(const float4*)&qs[c*128 + w0];
            float4 qbv= *(const float4*)&qs[c*128 + w0 + 4];
            float4 ka = *(const float4*)&ks[c*128 + v0];
            float4 kbv= *(const float4*)&ks[c*128 + v0 + 4];
            float qv[8] = {qa.x,qa.y,qa.z,qa.w,qbv.x,qbv.y,qbv.z,qbv.w};
            float kv[8] = {ka.x,ka.y,ka.z,ka.w,kbv.x,kbv.y,kbv.z,kbv.w};
#pragma unroll
            for (int j=0;j<8;j++)
#pragma unroll
                for (int i=0;i<8;i++) acc[j][i] += kv[j]*qv[i];
        }
#pragma unroll
        for (int j=0;j<8;j++)
#pragma unroll
            for (int i=0;i<8;i++) Et[(v0+j)*132 + w0+i] = acc[j][i];
    }
    __syncthreads();

    // ---- phase 2: softmax along key dim for each query w (exp stored, 1/sum kept) ----
    if (tid < 128) {
        int w = tid;
        float m = -1e30f;
#pragma unroll 4
        for (int kv=0; kv<128; kv++) m = fmaxf(m, Et[kv*132 + w]);
        float s = 0.f;
#pragma unroll 4
        for (int kv=0; kv<128; kv++) {
            float e = __expf(Et[kv*132 + w] - m);
            Et[kv*132 + w] = e;
            s += e;
        }
        ss[w] = 1.0f / s;
    }
    __syncthreads();

    // ---- phase 3: o[c][w] = (sum_kv Et[kv][w]*vs[c][kv]) * ss[w] ----
    {
        int w0 = (tid & 15) * 8;    // 8 queries
        int c0 = (tid >> 4) * 4;    // 4 channels
        float acc[4][8];
#pragma unroll
        for (int j=0;j<4;j++)
#pragma unroll
            for (int i=0;i<8;i++) acc[j][i] = 0.f;

        for (int kv=0; kv<128; kv++) {
            float4 a0 = *(const float4*)&Et[kv*132 + w0];
            float4 a1 = *(const float4*)&Et[kv*132 + w0 + 4];
            float av[8] = {a0.x,a0.y,a0.z,a0.w,a1.x,a1.y,a1.z,a1.w};
#pragma unroll
            for (int j=0;j<4;j++) {
                float vvv = vs[(c0+j)*128 + kv];
#pragma unroll
                for (int i=0;i<8;i++) acc[j][i] += vvv*av[i];
            }
        }

        float g = gamma[0];
#pragma unroll
        for (int j=0;j<4;j++) {
            size_t base = ((size_t)(b*CC + hd*64 + c0 + j)*HH + row)*WW + w0;
            if (mode == 0) {
#pragma unroll
                for (int i=0;i<8;i++) outp[base+i] = acc[j][i]*ss[w0+i];
            } else {
#pragma unroll
                for (int i=0;i<8;i++) {
                    float o = acc[j][i]*ss[w0+i] + scr[base+i];
                    outp[base+i] = g*o + x[base+i];
                }
            }
        }
    }
}

// ---------------- host ----------------
extern "C" void kernel_launch(void* const* d_in, const int* in_sizes, int n_in,
                              void* d_out, int out_size)
{
    const float* x     = (const float*)d_in[0];
    const float* Wq    = (const float*)d_in[1];
    const float* bq    = (const float*)d_in[2];
    const float* Wk    = (const float*)d_in[3];
    const float* bk    = (const float*)d_in[4];
    const float* Wv    = (const float*)d_in[5];
    const float* bv    = (const float*)d_in[6];
    const float* gamma = (const float*)d_in[7];
    float* out = (float*)d_out;

    float *pq, *pk, *pv, *pqT, *pkT, *pvT, *poh;
    cudaGetSymbolAddress((void**)&pq,  g_q);
    cudaGetSymbolAddress((void**)&pk,  g_k);
    cudaGetSymbolAddress((void**)&pv,  g_v);
    cudaGetSymbolAddress((void**)&pqT, g_qT);
    cudaGetSymbolAddress((void**)&pkT, g_kT);
    cudaGetSymbolAddress((void**)&pvT, g_vT);
    cudaGetSymbolAddress((void**)&poh, g_oh);

    // projections
    proj_kernel<32,64,16,2,4><<<dim3(P/64, 1, BB), 256>>>(Wq, bq, x, pq, CQ, CC, P);
    proj_kernel<32,64,16,2,4><<<dim3(P/64, 1, BB), 256>>>(Wk, bk, x, pk, CQ, CC, P);
    proj_kernel<64,64,16,4,4><<<dim3(P/64, CC/64, BB), 256>>>(Wv, bv, x, pv, CC, CC, P);

    // transposes for the vertical pass
    transpose_kernel<<<dim3(4,4,BB*CQ), 256>>>(pq, pqT);
    transpose_kernel<<<dim3(4,4,BB*CQ), 256>>>(pk, pkT);
    transpose_kernel<<<dim3(4,4,BB*CC), 256>>>(pv, pvT);

    // attention
    const int SMEM = (1024 + 1024 + 8192 + 128*132 + 128) * 4;  // ~106.5 KB
    cudaFuncSetAttribute(attn_kernel, cudaFuncAttributeMaxDynamicSharedMemorySize, SMEM);

    // horizontal: o_h -> scratch
    attn_kernel<<<dim3(HH, BB*NH), 256, SMEM>>>(pq, pk, pv, nullptr, nullptr, gamma, poh, 0);
    // vertical (on transposed arrays) + fused epilogue: out = gamma*(o_h+o_v)+x
    attn_kernel<<<dim3(WW, BB*NH), 256, SMEM>>>(pqT, pkT, pvT, poh, x, gamma, out, 1);
}